// round 9
// baseline (speedup 1.0000x reference)
#include <cuda_runtime.h>
#include <stdint.h>

#define T_DIM 8
#define C_DIM 4
#define H_DIM 1024
#define W_DIM 1024
#define NIMG  (T_DIM * C_DIM)
#define NGRID 16
#define NCELLS (NGRID * NGRID)
#define THRESH 0.65f
#define NUM_FG 40
#define NUM_BG 1
#define MAX_PTS 42
#define ROW_F4 (W_DIM / 4)   // 256
#define BLOCKS_PER_IMG 32    // each block = half a cell-row (8 cells, one per warp)

// Scratch (__device__ globals). Each cell has exactly ONE writer warp, and the
// written value is a pure function of the inputs -> plain stores are idempotent
// across graph replays (no init kernel, no atomics needed).
__device__ unsigned long long g_cmax[NIMG * NCELLS]; // (score_bits<<32) | ~flat_idx  (max, min-idx tie-break)
__device__ unsigned long long g_cmin[NIMG * NCELLS]; // (score_bits<<32) |  flat_idx  (min, min-idx tie-break)
__device__ unsigned int       g_cnt[NIMG];           // arrival counters; last block resets to 0

static __device__ __forceinline__ unsigned long long umaxll(unsigned long long a, unsigned long long b){ return a > b ? a : b; }
static __device__ __forceinline__ unsigned long long uminll(unsigned long long a, unsigned long long b){ return a < b ? a : b; }

__global__ void __launch_bounds__(256)
fused_kernel(const float* __restrict__ sim,
             const int*   __restrict__ ori,
             float*       __restrict__ out,
             int write_nums)
{
    const int blk  = blockIdx.x;             // 0..1023
    const int img  = blk >> 5;               // 32 images
    const int sub  = blk & 31;
    const int cy   = sub >> 1;               // cell row 0..15
    const int half = sub & 1;                // left/right half of the row
    const int tid  = threadIdx.x;
    const int w    = tid >> 5;               // warp 0..7: owns cell cx = half*8 + w
    const int lane = tid & 31;
    const int cx   = half * 8 + w;
    const float4* base = (const float4*)(sim + (size_t)img * (H_DIM * W_DIM));

    // Lane geometry inside a chunk (8 rows x 64 cols of one cell):
    //   it in 0..3 covers row (c*8 + it*2 + rsub); lanes 0-15 / 16-31 each cover
    //   a full 256B row -> every LDG.128 is perfectly coalesced (2 rows x 256B).
    const int rsub = lane >> 4;              // 0..1
    const int csub = lane & 15;              // 0..15

    // float4 index of (chunk c, it=0) for this lane:
    #define A0(c) ((cy * 64 + (c) * 8 + rsub) * ROW_F4 + cx * 16 + csub)

    float4 cur[4], nxt[4];
    {
        const int a = A0(0);
        #pragma unroll
        for (int it = 0; it < 4; it++) cur[it] = __ldcs(base + a + it * (2 * ROW_F4));
    }

    float vmax = -1.0f, vmin = 2.0f;
    int bqmax = 0, bqmin = 0;

    #pragma unroll
    for (int c = 0; c < 8; c++) {
        if (c < 7) {                         // software-pipelined prefetch of next chunk
            const int a = A0(c + 1);
            #pragma unroll
            for (int it = 0; it < 4; it++) nxt[it] = __ldcs(base + a + it * (2 * ROW_F4));
        }
        // 16-value max/min trees over the current chunk
        float mx0 = fmaxf(fmaxf(cur[0].x, cur[0].y), fmaxf(cur[0].z, cur[0].w));
        float mx1 = fmaxf(fmaxf(cur[1].x, cur[1].y), fmaxf(cur[1].z, cur[1].w));
        float mx2 = fmaxf(fmaxf(cur[2].x, cur[2].y), fmaxf(cur[2].z, cur[2].w));
        float mx3 = fmaxf(fmaxf(cur[3].x, cur[3].y), fmaxf(cur[3].z, cur[3].w));
        float cmax = fmaxf(fmaxf(mx0, mx1), fmaxf(mx2, mx3));
        float mn0 = fminf(fminf(cur[0].x, cur[0].y), fminf(cur[0].z, cur[0].w));
        float mn1 = fminf(fminf(cur[1].x, cur[1].y), fminf(cur[1].z, cur[1].w));
        float mn2 = fminf(fminf(cur[2].x, cur[2].y), fminf(cur[2].z, cur[2].w));
        float mn3 = fminf(fminf(cur[3].x, cur[3].y), fminf(cur[3].z, cur[3].w));
        float cmin = fminf(fminf(mn0, mn1), fminf(mn2, mn3));
        // Chunk-granular deferred tracking. Strict compare keeps the FIRST
        // chunk achieving the extremum (chunks ascend in flat index).
        if (cmax > vmax) { vmax = cmax; bqmax = c; }
        if (cmin < vmin) { vmin = cmin; bqmin = c; }
        if (c < 7) {
            #pragma unroll
            for (int it = 0; it < 4; it++) cur[it] = nxt[it];
        }
    }

    // Warp reduce values.
    float wmax = vmax, wmin = vmin;
    #pragma unroll
    for (int off = 16; off; off >>= 1) {
        wmax = fmaxf(wmax, __shfl_xor_sync(0xffffffffu, wmax, off));
        wmin = fminf(wmin, __shfl_xor_sync(0xffffffffu, wmin, off));
    }

    // Deferred index resolution: matching lanes re-load their best chunk
    // (64B each, L2-resident) and scan 16 values DESCENDING so overwrite
    // keeps the smallest flat index (reference first-occurrence semantics).
    unsigned candMax = 0xffffffffu, candMin = 0xffffffffu;
    if (vmax == wmax) {
        const int c = bqmax;
        const int a = A0(c);
        const int row0 = cy * 64 + c * 8 + rsub;
        const int col  = (cx * 16 + csub) * 4;
        #pragma unroll
        for (int it = 3; it >= 0; it--) {
            float4 v = __ldcg(base + a + it * (2 * ROW_F4));
            unsigned i0 = (unsigned)((row0 + it * 2) * W_DIM + col);
            if (v.w == wmax) candMax = i0 + 3;
            if (v.z == wmax) candMax = i0 + 2;
            if (v.y == wmax) candMax = i0 + 1;
            if (v.x == wmax) candMax = i0;
        }
    }
    if (vmin == wmin) {
        const int c = bqmin;
        const int a = A0(c);
        const int row0 = cy * 64 + c * 8 + rsub;
        const int col  = (cx * 16 + csub) * 4;
        #pragma unroll
        for (int it = 3; it >= 0; it--) {
            float4 v = __ldcg(base + a + it * (2 * ROW_F4));
            unsigned i0 = (unsigned)((row0 + it * 2) * W_DIM + col);
            if (v.w == wmin) candMin = i0 + 3;
            if (v.z == wmin) candMin = i0 + 2;
            if (v.y == wmin) candMin = i0 + 1;
            if (v.x == wmin) candMin = i0;
        }
    }
    #pragma unroll
    for (int off = 16; off; off >>= 1) {
        candMax = min(candMax, __shfl_xor_sync(0xffffffffu, candMax, off));
        candMin = min(candMin, __shfl_xor_sync(0xffffffffu, candMin, off));
    }

    if (lane == 0) {
        const int cell = cy * 16 + cx;
        g_cmax[img * NCELLS + cell] =
            ((unsigned long long)__float_as_uint(wmax) << 32) | (unsigned)(~candMax);
        g_cmin[img * NCELLS + cell] =
            ((unsigned long long)__float_as_uint(wmin) << 32) | candMin;
    }

    // ---------------- handoff: last of 32 blocks per image finalizes ----------------
    __threadfence();                        // push cell results to GPU scope
    __syncthreads();
    __shared__ int sLast;
    if (tid == 0) {
        unsigned prev = atomicAdd(&g_cnt[img], 1u);
        int last = (prev == BLOCKS_PER_IMG - 1);
        if (last) g_cnt[img] = 0;           // self-reset for next graph replay
        sLast = last;
    }
    __syncthreads();
    if (!sLast) return;
    __threadfence();                        // acquire side

    // ---------------- Phase 2: finalize (one block per image) ----------------
    const int t = img / C_DIM;
    const float sx = (float)ori[t * 2 + 1] / (float)W_DIM;
    const float sy = (float)ori[t * 2 + 0] / (float)H_DIM;

    __shared__ unsigned long long key[NCELLS];
    __shared__ unsigned long long sG[16];   // [0:8) img-max partials, [8:16) img-min partials

    unsigned long long pM = __ldcg(&g_cmax[img * NCELLS + tid]);
    unsigned long long pN = __ldcg(&g_cmin[img * NCELLS + tid]);
    unsigned bits = (unsigned)(pM >> 32);
    unsigned pidx = ~(unsigned)(pM & 0xffffffffull);
    bool valid = __uint_as_float(bits) > THRESH;   // fg cell iff its max exceeds threshold

    // Unique sort key: descending score, ascending cell id; invalid cells last (stable by cid).
    unsigned long long k = valid ? ((pM & 0xFFFFFFFF00000000ULL) | (unsigned)(255 - tid))
                                 : (unsigned long long)(unsigned)(255 - tid);
    key[tid] = k;

    // Image-global extrema.
    unsigned long long gm = pM, gn = pN;
    #pragma unroll
    for (int off = 16; off; off >>= 1) {
        gm = umaxll(gm, __shfl_xor_sync(0xffffffffu, gm, off));
        gn = uminll(gn, __shfl_xor_sync(0xffffffffu, gn, off));
    }
    if (lane == 0) { sG[w] = gm; sG[8 + w] = gn; }

    int nvalid = __syncthreads_count((int)valid);

    int rank = 0;
    #pragma unroll 8
    for (int j = 0; j < NCELLS; j++) rank += (key[j] > k) ? 1 : 0;

    bool any_fg  = (nvalid > 0);
    int fg_count = any_fg ? (nvalid < NUM_FG ? nvalid : NUM_FG) : 1;

    float* o = out + (size_t)img * MAX_PTS * 4;
    if (tid < MAX_PTS * 4) o[tid] = 0.0f;   // 168 < 256: full zero of this image's block
    __syncthreads();

    if (any_fg) {
        if (rank < NUM_FG && valid) {
            float s  = __uint_as_float(bits);
            float px = (float)(pidx % W_DIM);
            float py = (float)(pidx / W_DIM);
            float* r = o + rank * 4;
            r[0] = px * sx; r[1] = py * sy; r[2] = s; r[3] = 1.0f;
        }
    } else if (tid == 0) {
        unsigned long long m = sG[0];
        #pragma unroll
        for (int i = 1; i < 8; i++) m = umaxll(m, sG[i]);
        unsigned gb = (unsigned)(m >> 32);
        unsigned gi = ~(unsigned)(m & 0xffffffffull);
        o[0] = (float)(gi % W_DIM) * sx;
        o[1] = (float)(gi / W_DIM) * sy;
        o[2] = __uint_as_float(gb);
        o[3] = 1.0f;
    }

    if (tid == 0) {
        unsigned long long n = sG[8];
        #pragma unroll
        for (int i = 1; i < 8; i++) n = uminll(n, sG[8 + i]);
        unsigned bb = (unsigned)(n >> 32);
        unsigned bi = (unsigned)(n & 0xffffffffull);
        float* r = o + fg_count * 4;
        r[0] = (float)(bi % W_DIM) * sx;
        r[1] = (float)(bi / W_DIM) * sy;
        r[2] = __uint_as_float(bb);
        r[3] = 0.0f;
        if (write_nums) {
            float* nums = out + (size_t)NIMG * MAX_PTS * 4;
            nums[img] = (float)(fg_count + NUM_BG);
        }
    }
}

extern "C" void kernel_launch(void* const* d_in, const int* in_sizes, int n_in,
                              void* d_out, int out_size) {
    const float* sim = (const float*)d_in[0];
    // d_in[1] = category_ids (unused by the reference output)
    const int* ori = (const int*)d_in[2];

    int write_nums = (out_size >= NIMG * MAX_PTS * 4 + NIMG) ? 1 : 0;
    fused_kernel<<<NIMG * BLOCKS_PER_IMG, 256>>>(sim, ori, (float*)d_out, write_nums);
}

// round 10
// speedup vs baseline: 1.1370x; 1.1370x over previous
#include <cuda_runtime.h>
#include <stdint.h>

#define T_DIM 8
#define C_DIM 4
#define H_DIM 1024
#define W_DIM 1024
#define NIMG  (T_DIM * C_DIM)
#define NGRID 16
#define NCELLS (NGRID * NGRID)
#define THRESH 0.65f
#define NUM_FG 40
#define NUM_BG 1
#define MAX_PTS 42
#define ROW_F4 (W_DIM / 4)   // 256
#define BLOCKS_PER_IMG 16    // one block per cell-row (16 cells, 2 per warp)

// Scratch (__device__ globals). Each cell has exactly ONE writer warp, and the
// written value is a pure function of the inputs -> plain stores are idempotent
// across graph replays (no init kernel, no atomics needed).
__device__ unsigned long long g_cmax[NIMG * NCELLS]; // (score_bits<<32) | ~flat_idx  (max, min-idx tie-break)
__device__ unsigned long long g_cmin[NIMG * NCELLS]; // (score_bits<<32) |  flat_idx  (min, min-idx tie-break)
__device__ unsigned int       g_cnt[NIMG];           // arrival counters; last block resets to 0

static __device__ __forceinline__ unsigned long long umaxll(unsigned long long a, unsigned long long b){ return a > b ? a : b; }
static __device__ __forceinline__ unsigned long long uminll(unsigned long long a, unsigned long long b){ return a < b ? a : b; }

__global__ void __launch_bounds__(256)
fused_kernel(const float* __restrict__ sim,
             const int*   __restrict__ ori,
             float*       __restrict__ out,
             int write_nums)
{
    const int blk  = blockIdx.x;             // 0..511
    const int img  = blk >> 4;               // 32 images
    const int cy   = blk & 15;               // this block owns cell-row cy (16 cells)
    const int tid  = threadIdx.x;
    const int w    = tid >> 5;               // warp 0..7: owns cells cx = 2w, 2w+1
    const int lane = tid & 31;
    const float4* base = (const float4*)(sim + (size_t)img * (H_DIM * W_DIM));

    // Lane geometry inside a chunk (8 rows x 64 cols of one cell):
    //   it in 0..3 covers row pair (it*2 + rsub); lanes 0-15 / 16-31 each cover
    //   a full 256B row -> every LDG.128 is perfectly coalesced (2 rows x 256B).
    const int rsub = lane >> 4;              // 0..1
    const int csub = lane & 15;              // 0..15

    // q = 0..15 linear chunk id: cell cx = 2w + (q>>3), chunk c = q&7.
    // float4 index of (q, it=0) for this lane:
    #define A0(q) ((cy * 64 + ((q) & 7) * 8 + rsub) * ROW_F4 + (2 * w + ((q) >> 3)) * 16 + csub)

    // Depth-2 software pipeline: 3-buffer ring, loads issued 2 chunks ahead.
    float4 buf[3][4];
    {
        const int a0 = A0(0), a1 = A0(1);
        #pragma unroll
        for (int it = 0; it < 4; it++) buf[0][it] = __ldcs(base + a0 + it * (2 * ROW_F4));
        #pragma unroll
        for (int it = 0; it < 4; it++) buf[1][it] = __ldcs(base + a1 + it * (2 * ROW_F4));
    }

    #pragma unroll
    for (int cc = 0; cc < 2; cc++) {         // two cells per warp
        float vmax = 0.0f;                   // scores are in [0,1): 0.0f is a safe floor
        float vmin = __uint_as_float(0x7f800000u);  // +inf: safe ceiling, bit-monotone
        int bqmax = cc * 8, bqmin = cc * 8;

        #pragma unroll
        for (int c = 0; c < 8; c++) {
            const int q = cc * 8 + c;
            if (q < 14) {                    // prefetch 2 chunks ahead (crosses cell boundary)
                const int a = A0(q + 2);
                #pragma unroll
                for (int it = 0; it < 4; it++)
                    buf[(q + 2) % 3][it] = __ldcs(base + a + it * (2 * ROW_F4));
            }
            const float4* cur = buf[q % 3];
            // 16-value max/min trees over the current chunk
            float mx0 = fmaxf(fmaxf(cur[0].x, cur[0].y), fmaxf(cur[0].z, cur[0].w));
            float mx1 = fmaxf(fmaxf(cur[1].x, cur[1].y), fmaxf(cur[1].z, cur[1].w));
            float mx2 = fmaxf(fmaxf(cur[2].x, cur[2].y), fmaxf(cur[2].z, cur[2].w));
            float mx3 = fmaxf(fmaxf(cur[3].x, cur[3].y), fmaxf(cur[3].z, cur[3].w));
            float cmax = fmaxf(fmaxf(mx0, mx1), fmaxf(mx2, mx3));
            float mn0 = fminf(fminf(cur[0].x, cur[0].y), fminf(cur[0].z, cur[0].w));
            float mn1 = fminf(fminf(cur[1].x, cur[1].y), fminf(cur[1].z, cur[1].w));
            float mn2 = fminf(fminf(cur[2].x, cur[2].y), fminf(cur[2].z, cur[2].w));
            float mn3 = fminf(fminf(cur[3].x, cur[3].y), fminf(cur[3].z, cur[3].w));
            float cmin = fminf(fminf(mn0, mn1), fminf(mn2, mn3));
            // Chunk-granular deferred tracking. Strict compare keeps the FIRST
            // chunk achieving the extremum (chunks ascend in flat index).
            if (cmax > vmax) { vmax = cmax; bqmax = q; }
            if (cmin < vmin) { vmin = cmin; bqmin = q; }
        }

        // Warp value reductions via single-instruction REDUX (scores positive ->
        // unsigned bit order == float order).
        float wmax = __uint_as_float(__reduce_max_sync(0xffffffffu, __float_as_uint(vmax)));
        float wmin = __uint_as_float(__reduce_min_sync(0xffffffffu, __float_as_uint(vmin)));

        // Deferred index resolution: matching lanes re-load their best chunk
        // (64B each, L2-resident) and scan 16 values DESCENDING so overwrite
        // keeps the smallest flat index (reference first-occurrence semantics).
        unsigned candMax = 0xffffffffu, candMin = 0xffffffffu;
        if (vmax == wmax) {
            const int q = bqmax;
            const int a = A0(q);
            const int row0 = cy * 64 + (q & 7) * 8 + rsub;
            const int col  = ((2 * w + (q >> 3)) * 16 + csub) * 4;
            #pragma unroll
            for (int it = 3; it >= 0; it--) {
                float4 v = __ldcg(base + a + it * (2 * ROW_F4));
                unsigned i0 = (unsigned)((row0 + it * 2) * W_DIM + col);
                if (v.w == wmax) candMax = i0 + 3;
                if (v.z == wmax) candMax = i0 + 2;
                if (v.y == wmax) candMax = i0 + 1;
                if (v.x == wmax) candMax = i0;
            }
        }
        if (vmin == wmin) {
            const int q = bqmin;
            const int a = A0(q);
            const int row0 = cy * 64 + (q & 7) * 8 + rsub;
            const int col  = ((2 * w + (q >> 3)) * 16 + csub) * 4;
            #pragma unroll
            for (int it = 3; it >= 0; it--) {
                float4 v = __ldcg(base + a + it * (2 * ROW_F4));
                unsigned i0 = (unsigned)((row0 + it * 2) * W_DIM + col);
                if (v.w == wmin) candMin = i0 + 3;
                if (v.z == wmin) candMin = i0 + 2;
                if (v.y == wmin) candMin = i0 + 1;
                if (v.x == wmin) candMin = i0;
            }
        }
        candMax = __reduce_min_sync(0xffffffffu, candMax);
        candMin = __reduce_min_sync(0xffffffffu, candMin);

        if (lane == 0) {
            const int cell = cy * 16 + 2 * w + cc;
            g_cmax[img * NCELLS + cell] =
                ((unsigned long long)__float_as_uint(wmax) << 32) | (unsigned)(~candMax);
            g_cmin[img * NCELLS + cell] =
                ((unsigned long long)__float_as_uint(wmin) << 32) | candMin;
        }
    }

    // ---------------- handoff: last of 16 blocks per image finalizes ----------------
    if (lane == 0) __threadfence();         // only the storing lanes need the release fence
    __syncthreads();
    __shared__ int sLast;
    if (tid == 0) {
        unsigned prev = atomicAdd(&g_cnt[img], 1u);
        int last = (prev == BLOCKS_PER_IMG - 1);
        if (last) g_cnt[img] = 0;           // self-reset for next graph replay
        sLast = last;
    }
    __syncthreads();
    if (!sLast) return;
    __threadfence();                        // acquire side

    // ---------------- Phase 2: finalize (one block per image) ----------------
    const int t = img / C_DIM;
    const float sx = (float)ori[t * 2 + 1] / (float)W_DIM;
    const float sy = (float)ori[t * 2 + 0] / (float)H_DIM;

    __shared__ unsigned long long key[NCELLS];
    __shared__ unsigned long long sG[16];   // [0:8) img-max partials, [8:16) img-min partials

    unsigned long long pM = __ldcg(&g_cmax[img * NCELLS + tid]);
    unsigned long long pN = __ldcg(&g_cmin[img * NCELLS + tid]);
    unsigned bits = (unsigned)(pM >> 32);
    unsigned pidx = ~(unsigned)(pM & 0xffffffffull);
    bool valid = __uint_as_float(bits) > THRESH;   // fg cell iff its max exceeds threshold

    // Unique sort key: descending score, ascending cell id; invalid cells last (stable by cid).
    unsigned long long k = valid ? ((pM & 0xFFFFFFFF00000000ULL) | (unsigned)(255 - tid))
                                 : (unsigned long long)(unsigned)(255 - tid);
    key[tid] = k;

    // Image-global extrema.
    unsigned long long gm = pM, gn = pN;
    #pragma unroll
    for (int off = 16; off; off >>= 1) {
        gm = umaxll(gm, __shfl_xor_sync(0xffffffffu, gm, off));
        gn = uminll(gn, __shfl_xor_sync(0xffffffffu, gn, off));
    }
    if (lane == 0) { sG[w] = gm; sG[8 + w] = gn; }

    int nvalid = __syncthreads_count((int)valid);

    int rank = 0;
    #pragma unroll 8
    for (int j = 0; j < NCELLS; j++) rank += (key[j] > k) ? 1 : 0;

    bool any_fg  = (nvalid > 0);
    int fg_count = any_fg ? (nvalid < NUM_FG ? nvalid : NUM_FG) : 1;

    float* o = out + (size_t)img * MAX_PTS * 4;
    if (tid < MAX_PTS * 4) o[tid] = 0.0f;   // 168 < 256: full zero of this image's block
    __syncthreads();

    if (any_fg) {
        if (rank < NUM_FG && valid) {
            float s  = __uint_as_float(bits);
            float px = (float)(pidx % W_DIM);
            float py = (float)(pidx / W_DIM);
            float* r = o + rank * 4;
            r[0] = px * sx; r[1] = py * sy; r[2] = s; r[3] = 1.0f;
        }
    } else if (tid == 0) {
        unsigned long long m = sG[0];
        #pragma unroll
        for (int i = 1; i < 8; i++) m = umaxll(m, sG[i]);
        unsigned gb = (unsigned)(m >> 32);
        unsigned gi = ~(unsigned)(m & 0xffffffffull);
        o[0] = (float)(gi % W_DIM) * sx;
        o[1] = (float)(gi / W_DIM) * sy;
        o[2] = __uint_as_float(gb);
        o[3] = 1.0f;
    }

    if (tid == 0) {
        unsigned long long n = sG[8];
        #pragma unroll
        for (int i = 1; i < 8; i++) n = uminll(n, sG[8 + i]);
        unsigned bb = (unsigned)(n >> 32);
        unsigned bi = (unsigned)(n & 0xffffffffull);
        float* r = o + fg_count * 4;
        r[0] = (float)(bi % W_DIM) * sx;
        r[1] = (float)(bi / W_DIM) * sy;
        r[2] = __uint_as_float(bb);
        r[3] = 0.0f;
        if (write_nums) {
            float* nums = out + (size_t)NIMG * MAX_PTS * 4;
            nums[img] = (float)(fg_count + NUM_BG);
        }
    }
}

extern "C" void kernel_launch(void* const* d_in, const int* in_sizes, int n_in,
                              void* d_out, int out_size) {
    const float* sim = (const float*)d_in[0];
    // d_in[1] = category_ids (unused by the reference output)
    const int* ori = (const int*)d_in[2];

    int write_nums = (out_size >= NIMG * MAX_PTS * 4 + NIMG) ? 1 : 0;
    fused_kernel<<<NIMG * BLOCKS_PER_IMG, 256>>>(sim, ori, (float*)d_out, write_nums);
}